// round 2
// baseline (speedup 1.0000x reference)
#include <cuda_runtime.h>
#include <cuda_bf16.h>

// ---------------- static scratch (no runtime allocation allowed) ----------------
#define NMAX 50048
#define EMAX 1664000
#define GMAXG 512

__device__ float g_feat[(size_t)NMAX * 245];   // CNN flattened features
__device__ float g_h0[(size_t)NMAX * 128];     // encoder output (APPNP h0)
__device__ float g_h1[(size_t)NMAX * 128];     // propagated h (reused for h2)
__device__ float g_agg[(size_t)NMAX * 128];    // scatter accumulator
__device__ float g_deg[NMAX];
__device__ float g_dinv[NMAX];
__device__ float g_nrm[EMAX];                  // 0.2 * dinv[row]*w*dinv[col]
__device__ float g_bnsum[128];
__device__ float g_bnsq[128];
__device__ float g_ab[256];                    // [0:128)=scale a, [128:256)=shift b
__device__ float g_gsum[GMAXG * 128];
__device__ float g_gcnt[GMAXG];

// ---------------- zero init ----------------
__global__ void k_zero(int n) {
    int i = blockIdx.x * blockDim.x + threadIdx.x;
    int tot = n * 128;
    if (i < tot) g_agg[i] = 0.f;
    if (i < n) g_deg[i] = 0.f;
    if (i < 128) { g_bnsum[i] = 0.f; g_bnsq[i] = 0.f; }
    if (i < GMAXG * 128) g_gsum[i] = 0.f;
    if (i < GMAXG) g_gcnt[i] = 0.f;
}

// ---------------- CNN node encoder: conv1(3x3,s1)+relu -> conv2(5x5,s2)+relu ----------------
// one block per node, 128 threads; everything smem-resident
__global__ __launch_bounds__(128) void k_cnn(
    const float* __restrict__ x,
    const float* __restrict__ c1w, const float* __restrict__ c1b,
    const float* __restrict__ c2w, const float* __restrict__ c2b, int n)
{
    __shared__ float xs[1083];        // 3*19*19
    __shared__ float c1s[2312];       // 8*17*17
    __shared__ float w1[216 + 8];
    __shared__ float w2[1000 + 5];

    int node = blockIdx.x;
    if (node >= n) return;
    int t = threadIdx.x;

    const float* xp = x + (size_t)node * 1083;
    for (int i = t; i < 1083; i += 128) xs[i] = xp[i];
    for (int i = t; i < 216; i += 128) w1[i] = c1w[i];
    if (t < 8) w1[216 + t] = c1b[t];
    for (int i = t; i < 1000; i += 128) w2[i] = c2w[i];
    if (t < 5) w2[1000 + t] = c2b[t];
    __syncthreads();

    // conv1: out [8,17,17]
    for (int o = t; o < 2312; o += 128) {
        int oc = o / 289;
        int rem = o - oc * 289;
        int oy = rem / 17;
        int ox = rem - oy * 17;
        const float* wp = w1 + oc * 27;
        const float* xb = xs + oy * 19 + ox;
        float s = w1[216 + oc];
#pragma unroll
        for (int ic = 0; ic < 3; ic++)
#pragma unroll
            for (int ky = 0; ky < 3; ky++)
#pragma unroll
                for (int kx = 0; kx < 3; kx++)
                    s += xb[ic * 361 + ky * 19 + kx] * wp[ic * 9 + ky * 3 + kx];
        c1s[o] = fmaxf(s, 0.f);
    }
    __syncthreads();

    // conv2: out [5,7,7] stride 2, write flattened feature
    float* fp = g_feat + (size_t)node * 245;
    for (int o = t; o < 245; o += 128) {
        int oc = o / 49;
        int rem = o - oc * 49;
        int oy = rem / 7;
        int ox = rem - oy * 7;
        const float* wp = w2 + oc * 200;
        const float* ib = c1s + (oy * 2) * 17 + ox * 2;
        float s = w2[1000 + oc];
#pragma unroll
        for (int ic = 0; ic < 8; ic++)
#pragma unroll
            for (int ky = 0; ky < 5; ky++)
#pragma unroll
                for (int kx = 0; kx < 5; kx++)
                    s += ib[ic * 289 + ky * 17 + kx] * wp[ic * 25 + ky * 5 + kx];
        fp[o] = fmaxf(s, 0.f);
    }
}

// ---------------- degree / dinv / edge norm (indices are int32!) ----------------
__global__ void k_deg(const int* __restrict__ ei, const float* __restrict__ ea, int E) {
    int e = blockIdx.x * blockDim.x + threadIdx.x;
    if (e >= E) return;
    int c = ei[E + e];
    atomicAdd(&g_deg[c], ea[e]);
}

__global__ void k_dinv(int n) {
    int i = blockIdx.x * blockDim.x + threadIdx.x;
    if (i >= n) return;
    float d = g_deg[i];
    g_dinv[i] = (d > 0.f) ? rsqrtf(d) : 0.f;
}

__global__ void k_norm(const int* __restrict__ ei, const float* __restrict__ ea, int E) {
    int e = blockIdx.x * blockDim.x + threadIdx.x;
    if (e >= E) return;
    int r = ei[e];
    int c = ei[E + e];
    // fold (1 - alpha) = 0.2 into the edge weight (linear per hop)
    g_nrm[e] = 0.2f * g_dinv[r] * ea[e] * g_dinv[c];
}

// ---------------- l1: feat[n,245] @ l1w.T[245,128] + b, relu -> h0 ----------------
__global__ __launch_bounds__(256) void k_l1(const float* __restrict__ l1w,
                                            const float* __restrict__ l1b, int n)
{
    __shared__ float As[16][128];
    __shared__ float Bs[16][128];
    int t = threadIdx.x;          // 256 threads
    int tx = t & 15, ty = t >> 4; // 16x16
    float acc[8][8];
#pragma unroll
    for (int i = 0; i < 8; i++)
#pragma unroll
        for (int j = 0; j < 8; j++) acc[i][j] = 0.f;

    int rowBase = blockIdx.x * 128;
    for (int k0 = 0; k0 < 245; k0 += 16) {
#pragma unroll
        for (int i = 0; i < 8; i++) {
            int e = t + i * 256;       // 0..2047
            int m = e >> 4, kk = e & 15;
            int node = rowBase + m, k = k0 + kk;
            As[kk][m] = (node < n && k < 245) ? g_feat[(size_t)node * 245 + k] : 0.f;
            Bs[kk][m] = (k < 245) ? l1w[m * 245 + k] : 0.f;  // m doubles as output col j
        }
        __syncthreads();
#pragma unroll
        for (int kk = 0; kk < 16; kk++) {
            float a[8], b[8];
#pragma unroll
            for (int i = 0; i < 8; i++) a[i] = As[kk][ty + i * 16];
#pragma unroll
            for (int j = 0; j < 8; j++) b[j] = Bs[kk][tx + j * 16];
#pragma unroll
            for (int i = 0; i < 8; i++)
#pragma unroll
                for (int j = 0; j < 8; j++) acc[i][j] += a[i] * b[j];
        }
        __syncthreads();
    }
#pragma unroll
    for (int i = 0; i < 8; i++) {
        int node = rowBase + ty + i * 16;
        if (node >= n) continue;
#pragma unroll
        for (int j = 0; j < 8; j++) {
            int col = tx + j * 16;
            g_h0[(size_t)node * 128 + col] = fmaxf(acc[i][j] + l1b[col], 0.f);
        }
    }
}

// ---------------- APPNP hop: agg[col] += nrm[e] * h[row] (one warp per edge) ----------------
__global__ void k_hop(int src, const int* __restrict__ ei, int E) {
    int idx = blockIdx.x * blockDim.x + threadIdx.x;
    int e = idx >> 5;
    if (e >= E) return;
    int g = idx & 31;
    const float* hin = src ? g_h1 : g_h0;
    int r = ei[e];
    int c = ei[E + e];
    float nv = g_nrm[e];
    float4 v = ((const float4*)hin)[(size_t)r * 32 + g];
    float* ap = g_agg + (size_t)c * 128 + g * 4;
    atomicAdd(ap + 0, v.x * nv);
    atomicAdd(ap + 1, v.y * nv);
    atomicAdd(ap + 2, v.z * nv);
    atomicAdd(ap + 3, v.w * nv);
}

// ---------------- hop1 update: h1 = agg + 0.8*h0 ; re-zero agg for hop2 ----------------
__global__ void k_update1(int n) {
    int i = blockIdx.x * blockDim.x + threadIdx.x;
    if (i >= n * 128) return;
    g_h1[i] = g_agg[i] + 0.8f * g_h0[i];
    g_agg[i] = 0.f;
}

// ---------------- hop2 update fused with BN stats (channel-stationary) ----------------
__global__ __launch_bounds__(256) void k_update2_bn(int n) {
    int c = threadIdx.x & 127;
    int sub = threadIdx.x >> 7;    // 0/1
    int n0 = blockIdx.x * 128;
    float s = 0.f, sq = 0.f;
    for (int k = sub; k < 128; k += 2) {
        int node = n0 + k;
        if (node < n) {
            size_t i = (size_t)node * 128 + c;
            float v = g_agg[i] + 0.8f * g_h0[i];
            g_h1[i] = v;   // h2 reuses h1 buffer
            s += v; sq += v * v;
        }
    }
    __shared__ float ss[256], sqq[256];
    ss[threadIdx.x] = s; sqq[threadIdx.x] = sq;
    __syncthreads();
    if (threadIdx.x < 128) {
        atomicAdd(&g_bnsum[c], ss[threadIdx.x] + ss[threadIdx.x + 128]);
        atomicAdd(&g_bnsq[c], sqq[threadIdx.x] + sqq[threadIdx.x + 128]);
    }
}

__global__ void k_bnfin(const float* __restrict__ gamma, const float* __restrict__ beta,
                        float invN) {
    int c = threadIdx.x;
    float mean = g_bnsum[c] * invN;
    float var = g_bnsq[c] * invN - mean * mean;
    float inv = rsqrtf(var + 1e-5f);
    float a = gamma[c] * inv;
    g_ab[c] = a;
    g_ab[128 + c] = beta[c] - mean * a;
}

// ---------------- normalize + write node_x + pool scatter ----------------
__global__ void k_pool(const int* __restrict__ batch, float* __restrict__ out, int n) {
    int idx = blockIdx.x * blockDim.x + threadIdx.x;
    if (idx >= n * 32) return;
    int node = idx >> 5, q = idx & 31;
    int c = q * 4;
    float4 v = ((const float4*)g_h1)[idx];
    float4 r;
    r.x = v.x * g_ab[c + 0] + g_ab[128 + c + 0];
    r.y = v.y * g_ab[c + 1] + g_ab[128 + c + 1];
    r.z = v.z * g_ab[c + 2] + g_ab[128 + c + 2];
    r.w = v.w * g_ab[c + 3] + g_ab[128 + c + 3];
    ((float4*)out)[640 + idx] = r;   // node_x starts at float offset 2560
    int g = batch[node];
    float* gp = g_gsum + (size_t)g * 128 + c;
    atomicAdd(gp + 0, r.x);
    atomicAdd(gp + 1, r.y);
    atomicAdd(gp + 2, r.z);
    atomicAdd(gp + 3, r.w);
}

__global__ void k_gcnt(const int* __restrict__ batch, int n) {
    int i = blockIdx.x * blockDim.x + threadIdx.x;
    if (i >= n) return;
    atomicAdd(&g_gcnt[batch[i]], 1.0f);
}

// ---------------- graph MLP classifier ----------------
__global__ __launch_bounds__(64) void k_mlp(const float* __restrict__ l2w,
                                            const float* __restrict__ l2b,
                                            const float* __restrict__ l3w,
                                            const float* __restrict__ l3b,
                                            float* __restrict__ out) {
    int g = blockIdx.x, t = threadIdx.x;   // 64 threads
    __shared__ float gx[128], hid[64];
    float cnt = fmaxf(g_gcnt[g], 1.f);
    float ic = 1.f / cnt;
    gx[t]      = g_gsum[(size_t)g * 128 + t] * ic;
    gx[t + 64] = g_gsum[(size_t)g * 128 + 64 + t] * ic;
    __syncthreads();
    float s = l2b[t];
    const float* wr = l2w + t * 128;
#pragma unroll 8
    for (int c = 0; c < 128; c++) s += gx[c] * wr[c];
    hid[t] = fmaxf(s, 0.f);
    __syncthreads();
    if (t < 5) {
        float s2 = l3b[t];
        const float* wr3 = l3w + t * 64;
#pragma unroll 8
        for (int j = 0; j < 64; j++) s2 += hid[j] * wr3[j];
        out[g * 5 + t] = s2;
    }
}

// ---------------- launcher ----------------
extern "C" void kernel_launch(void* const* d_in, const int* in_sizes, int n_in,
                              void* d_out, int out_size) {
    // inputs: x, edge_index, edge_attr, batch, [num_graphs], c1w, c1b, c2w, c2b,
    //         l1w, l1b, gamma, beta, l2w, l2b, l3w, l3b
    int wb = (n_in > 4 && in_sizes[4] == 216) ? 4 : 5;  // detect scalar num_graphs presence

    const float* x     = (const float*)d_in[0];
    const int*   ei    = (const int*)d_in[1];     // int32 (jax x64 disabled)
    const float* ea    = (const float*)d_in[2];
    const int*   batch = (const int*)d_in[3];
    const float* c1w = (const float*)d_in[wb + 0];
    const float* c1b = (const float*)d_in[wb + 1];
    const float* c2w = (const float*)d_in[wb + 2];
    const float* c2b = (const float*)d_in[wb + 3];
    const float* l1w = (const float*)d_in[wb + 4];
    const float* l1b = (const float*)d_in[wb + 5];
    const float* gam = (const float*)d_in[wb + 6];
    const float* bet = (const float*)d_in[wb + 7];
    const float* l2w = (const float*)d_in[wb + 8];
    const float* l2b = (const float*)d_in[wb + 9];
    const float* l3w = (const float*)d_in[wb + 10];
    const float* l3b = (const float*)d_in[wb + 11];

    int n = in_sizes[0] / 1083;       // 50000
    int E = in_sizes[1] / 2;          // 1600000
    int G = (out_size - n * 128) / 5; // 512
    float* out = (float*)d_out;

    k_zero<<<(n * 128 + 255) / 256, 256>>>(n);
    k_cnn<<<n, 128>>>(x, c1w, c1b, c2w, c2b, n);
    k_deg<<<(E + 255) / 256, 256>>>(ei, ea, E);
    k_dinv<<<(n + 255) / 256, 256>>>(n);
    k_norm<<<(E + 255) / 256, 256>>>(ei, ea, E);
    k_l1<<<(n + 127) / 128, 256>>>(l1w, l1b, n);

    int hopBlocks = (E * 32 + 255) / 256;
    k_hop<<<hopBlocks, 256>>>(0, ei, E);
    k_update1<<<(n * 128 + 255) / 256, 256>>>(n);
    k_hop<<<hopBlocks, 256>>>(1, ei, E);
    k_update2_bn<<<(n + 127) / 128, 256>>>(n);

    k_bnfin<<<1, 128>>>(gam, bet, 1.0f / (float)n);
    k_pool<<<(n * 32 + 255) / 256, 256>>>(batch, out, n);
    k_gcnt<<<(n + 255) / 256, 256>>>(batch, n);
    k_mlp<<<G, 64>>>(l2w, l2b, l3w, l3b, out);
}

// round 3
// speedup vs baseline: 1.4413x; 1.4413x over previous
#include <cuda_runtime.h>
#include <cuda_bf16.h>

// ---------------- static scratch (no runtime allocation allowed) ----------------
#define NMAX 50048
#define EMAX 1664000
#define GMAXG 512

__device__ float g_feat[(size_t)NMAX * 245];   // CNN flattened features
__device__ float g_h0[(size_t)NMAX * 128];     // encoder output (APPNP h0)
__device__ float g_h1[(size_t)NMAX * 128];     // hop1 result
__device__ float g_h2[(size_t)NMAX * 128];     // hop2 result
__device__ float g_deg[NMAX];
__device__ float g_dinv[NMAX];
__device__ int   g_indeg[NMAX];
__device__ int   g_off[NMAX + 1];
__device__ int   g_cur[NMAX];
__device__ int2  g_edge[EMAX];                 // (src, weight-bits), CSR by dest
__device__ float g_bnsum[128];
__device__ float g_bnsq[128];
__device__ float g_ab[256];                    // [0:128)=scale a, [128:256)=shift b
__device__ float g_gsum[GMAXG * 128];
__device__ float g_gcnt[GMAXG];

// ---------------- zero init (small now: no agg buffer) ----------------
__global__ void k_zero(int n) {
    int i = blockIdx.x * blockDim.x + threadIdx.x;
    if (i < n) { g_deg[i] = 0.f; g_indeg[i] = 0; }
    if (i < 128) { g_bnsum[i] = 0.f; g_bnsq[i] = 0.f; }
    if (i < GMAXG * 128) g_gsum[i] = 0.f;
    if (i < GMAXG) g_gcnt[i] = 0.f;
}

// ---------------- CNN node encoder: conv1(3x3,s1)+relu -> conv2(5x5,s2)+relu ----
// two nodes per block (256 threads); weights shared across both halves
__global__ __launch_bounds__(256) void k_cnn(
    const float* __restrict__ x,
    const float* __restrict__ c1w, const float* __restrict__ c1b,
    const float* __restrict__ c2w, const float* __restrict__ c2b, int n)
{
    __shared__ float xs[2][1083];     // 3*19*19
    __shared__ float c1s[2][2312];    // 8*17*17
    __shared__ float w1[216 + 8];
    __shared__ float w2[1000 + 5];

    int t = threadIdx.x;
    int half = t >> 7;                 // 0/1
    int tl = t & 127;
    int node = blockIdx.x * 2 + half;

    for (int i = t; i < 216; i += 256) w1[i] = c1w[i];
    if (t < 8) w1[216 + t] = c1b[t];
    for (int i = t; i < 1000; i += 256) w2[i] = c2w[i];
    if (t < 5) w2[1000 + t] = c2b[t];

    bool active = (node < n);
    if (active) {
        const float* xp = x + (size_t)node * 1083;
        for (int i = tl; i < 1083; i += 128) xs[half][i] = xp[i];
    }
    __syncthreads();

    if (active) {
        // conv1: out [8,17,17]
        for (int o = tl; o < 2312; o += 128) {
            int oc = o / 289;
            int rem = o - oc * 289;
            int oy = rem / 17;
            int ox = rem - oy * 17;
            const float* wp = w1 + oc * 27;
            const float* xb = xs[half] + oy * 19 + ox;
            float s = w1[216 + oc];
#pragma unroll
            for (int ic = 0; ic < 3; ic++)
#pragma unroll
                for (int ky = 0; ky < 3; ky++)
#pragma unroll
                    for (int kx = 0; kx < 3; kx++)
                        s += xb[ic * 361 + ky * 19 + kx] * wp[ic * 9 + ky * 3 + kx];
            c1s[half][o] = fmaxf(s, 0.f);
        }
    }
    __syncthreads();

    if (active) {
        // conv2: out [5,7,7] stride 2, write flattened feature
        float* fp = g_feat + (size_t)node * 245;
        for (int o = tl; o < 245; o += 128) {
            int oc = o / 49;
            int rem = o - oc * 49;
            int oy = rem / 7;
            int ox = rem - oy * 7;
            const float* wp = w2 + oc * 200;
            const float* ib = c1s[half] + (oy * 2) * 17 + ox * 2;
            float s = w2[1000 + oc];
#pragma unroll
            for (int ic = 0; ic < 8; ic++)
#pragma unroll
                for (int ky = 0; ky < 5; ky++)
#pragma unroll
                    for (int kx = 0; kx < 5; kx++)
                        s += ib[ic * 289 + ky * 17 + kx] * wp[ic * 25 + ky * 5 + kx];
            fp[o] = fmaxf(s, 0.f);
        }
    }
}

// ---------------- degree (weighted float + integer in-degree) ----------------
__global__ void k_deg(const int* __restrict__ ei, const float* __restrict__ ea, int E) {
    int e = blockIdx.x * blockDim.x + threadIdx.x;
    if (e >= E) return;
    int c = ei[E + e];
    atomicAdd(&g_deg[c], ea[e]);
    atomicAdd(&g_indeg[c], 1);
}

__global__ void k_dinv(int n) {
    int i = blockIdx.x * blockDim.x + threadIdx.x;
    if (i >= n) return;
    float d = g_deg[i];
    g_dinv[i] = (d > 0.f) ? rsqrtf(d) : 0.f;
}

// ---------------- single-block exclusive prefix scan of in-degrees ----------------
__global__ __launch_bounds__(1024) void k_scan(int n) {
    __shared__ int buf[2][1024];
    __shared__ int s_carry;
    int t = threadIdx.x;
    if (t == 0) s_carry = 0;
    __syncthreads();
    for (int base = 0; base < n; base += 1024) {
        int v = (base + t < n) ? g_indeg[base + t] : 0;
        buf[0][t] = v;
        __syncthreads();
        int src = 0;
#pragma unroll
        for (int d = 1; d < 1024; d <<= 1) {
            int val = buf[src][t];
            if (t >= d) val += buf[src][t - d];
            buf[1 - src][t] = val;
            src = 1 - src;
            __syncthreads();
        }
        int inc = buf[src][t];
        int carry = s_carry;
        if (base + t < n) {
            int excl = carry + inc - v;
            g_off[base + t] = excl;
            g_cur[base + t] = excl;
        }
        __syncthreads();
        if (t == 1023) s_carry = carry + inc;
        __syncthreads();
    }
    if (t == 0) g_off[n] = s_carry;
}

// ---------------- CSR build: norm + edge record placement ----------------
__global__ void k_csr(const int* __restrict__ ei, const float* __restrict__ ea, int E) {
    int e = blockIdx.x * blockDim.x + threadIdx.x;
    if (e >= E) return;
    int r = ei[e];
    int c = ei[E + e];
    // fold (1 - alpha) = 0.2 into the edge weight
    float nrm = 0.2f * g_dinv[r] * ea[e] * g_dinv[c];
    int pos = atomicAdd(&g_cur[c], 1);
    g_edge[pos] = make_int2(r, __float_as_int(nrm));
}

// ---------------- l1: feat[n,245] @ l1w.T[245,128] + b, relu -> h0 ----------------
__global__ __launch_bounds__(256) void k_l1(const float* __restrict__ l1w,
                                            const float* __restrict__ l1b, int n)
{
    __shared__ float As[16][128];
    __shared__ float Bs[16][128];
    int t = threadIdx.x;          // 256 threads
    int tx = t & 15, ty = t >> 4; // 16x16
    float acc[8][8];
#pragma unroll
    for (int i = 0; i < 8; i++)
#pragma unroll
        for (int j = 0; j < 8; j++) acc[i][j] = 0.f;

    int rowBase = blockIdx.x * 128;
    for (int k0 = 0; k0 < 245; k0 += 16) {
#pragma unroll
        for (int i = 0; i < 8; i++) {
            int e = t + i * 256;       // 0..2047
            int m = e >> 4, kk = e & 15;
            int node = rowBase + m, k = k0 + kk;
            As[kk][m] = (node < n && k < 245) ? g_feat[(size_t)node * 245 + k] : 0.f;
            Bs[kk][m] = (k < 245) ? l1w[m * 245 + k] : 0.f;  // m doubles as output col j
        }
        __syncthreads();
#pragma unroll
        for (int kk = 0; kk < 16; kk++) {
            float a[8], b[8];
#pragma unroll
            for (int i = 0; i < 8; i++) a[i] = As[kk][ty + i * 16];
#pragma unroll
            for (int j = 0; j < 8; j++) b[j] = Bs[kk][tx + j * 16];
#pragma unroll
            for (int i = 0; i < 8; i++)
#pragma unroll
                for (int j = 0; j < 8; j++) acc[i][j] += a[i] * b[j];
        }
        __syncthreads();
    }
#pragma unroll
    for (int i = 0; i < 8; i++) {
        int node = rowBase + ty + i * 16;
        if (node >= n) continue;
#pragma unroll
        for (int j = 0; j < 8; j++) {
            int col = tx + j * 16;
            g_h0[(size_t)node * 128 + col] = fmaxf(acc[i][j] + l1b[col], 0.f);
        }
    }
}

// ---------------- APPNP hop (gather form, no atomics): one warp per dest node ----
// hout[node] = sum_e nrm[e] * hin[src[e]] + 0.8 * h0[node]
__global__ __launch_bounds__(256) void k_hop(int which, int n) {
    int wid = (blockIdx.x * 256 + threadIdx.x) >> 5;
    int lane = threadIdx.x & 31;
    if (wid >= n) return;
    const float4* hin = (const float4*)(which ? g_h1 : g_h0);
    float4* hout = (float4*)(which ? g_h2 : g_h1);
    int off0 = g_off[wid], off1 = g_off[wid + 1];

    float4 acc = make_float4(0.f, 0.f, 0.f, 0.f);
    int e = off0;
    for (; e + 2 <= off1; e += 2) {                 // 2-wide for MLP
        int2 ra = g_edge[e];
        int2 rb = g_edge[e + 1];
        float4 v0 = hin[(size_t)ra.x * 32 + lane];
        float4 v1 = hin[(size_t)rb.x * 32 + lane];
        float w0 = __int_as_float(ra.y);
        float w1 = __int_as_float(rb.y);
        acc.x += w0 * v0.x; acc.y += w0 * v0.y; acc.z += w0 * v0.z; acc.w += w0 * v0.w;
        acc.x += w1 * v1.x; acc.y += w1 * v1.y; acc.z += w1 * v1.z; acc.w += w1 * v1.w;
    }
    if (e < off1) {
        int2 ra = g_edge[e];
        float4 v0 = hin[(size_t)ra.x * 32 + lane];
        float w0 = __int_as_float(ra.y);
        acc.x += w0 * v0.x; acc.y += w0 * v0.y; acc.z += w0 * v0.z; acc.w += w0 * v0.w;
    }
    float4 h0v = ((const float4*)g_h0)[(size_t)wid * 32 + lane];
    float4 o;
    o.x = acc.x + 0.8f * h0v.x;
    o.y = acc.y + 0.8f * h0v.y;
    o.z = acc.z + 0.8f * h0v.z;
    o.w = acc.w + 0.8f * h0v.w;
    hout[(size_t)wid * 32 + lane] = o;
}

// ---------------- BN stats over h2 (channel-stationary) ----------------
__global__ __launch_bounds__(256) void k_bnstats(int n) {
    int c = threadIdx.x & 127;
    int sub = threadIdx.x >> 7;    // 0/1
    int n0 = blockIdx.x * 128;
    float s = 0.f, sq = 0.f;
    for (int k = sub; k < 128; k += 2) {
        int node = n0 + k;
        if (node < n) {
            float v = g_h2[(size_t)node * 128 + c];
            s += v; sq += v * v;
        }
    }
    __shared__ float ss[256], sqq[256];
    ss[threadIdx.x] = s; sqq[threadIdx.x] = sq;
    __syncthreads();
    if (threadIdx.x < 128) {
        atomicAdd(&g_bnsum[c], ss[threadIdx.x] + ss[threadIdx.x + 128]);
        atomicAdd(&g_bnsq[c], sqq[threadIdx.x] + sqq[threadIdx.x + 128]);
    }
}

__global__ void k_bnfin(const float* __restrict__ gamma, const float* __restrict__ beta,
                        float invN) {
    int c = threadIdx.x;
    float mean = g_bnsum[c] * invN;
    float var = g_bnsq[c] * invN - mean * mean;
    float inv = rsqrtf(var + 1e-5f);
    float a = gamma[c] * inv;
    g_ab[c] = a;
    g_ab[128 + c] = beta[c] - mean * a;
}

// ---------------- normalize + write node_x + pool scatter ----------------
__global__ void k_pool(const int* __restrict__ batch, float* __restrict__ out, int n) {
    int idx = blockIdx.x * blockDim.x + threadIdx.x;
    if (idx >= n * 32) return;
    int node = idx >> 5, q = idx & 31;
    int c = q * 4;
    float4 v = ((const float4*)g_h2)[idx];
    float4 r;
    r.x = v.x * g_ab[c + 0] + g_ab[128 + c + 0];
    r.y = v.y * g_ab[c + 1] + g_ab[128 + c + 1];
    r.z = v.z * g_ab[c + 2] + g_ab[128 + c + 2];
    r.w = v.w * g_ab[c + 3] + g_ab[128 + c + 3];
    ((float4*)out)[640 + idx] = r;   // node_x starts at float offset 2560
    int g = batch[node];
    float* gp = g_gsum + (size_t)g * 128 + c;
    atomicAdd(gp + 0, r.x);
    atomicAdd(gp + 1, r.y);
    atomicAdd(gp + 2, r.z);
    atomicAdd(gp + 3, r.w);
}

__global__ void k_gcnt(const int* __restrict__ batch, int n) {
    int i = blockIdx.x * blockDim.x + threadIdx.x;
    if (i >= n) return;
    atomicAdd(&g_gcnt[batch[i]], 1.0f);
}

// ---------------- graph MLP classifier ----------------
__global__ __launch_bounds__(64) void k_mlp(const float* __restrict__ l2w,
                                            const float* __restrict__ l2b,
                                            const float* __restrict__ l3w,
                                            const float* __restrict__ l3b,
                                            float* __restrict__ out) {
    int g = blockIdx.x, t = threadIdx.x;   // 64 threads
    __shared__ float gx[128], hid[64];
    float cnt = fmaxf(g_gcnt[g], 1.f);
    float ic = 1.f / cnt;
    gx[t]      = g_gsum[(size_t)g * 128 + t] * ic;
    gx[t + 64] = g_gsum[(size_t)g * 128 + 64 + t] * ic;
    __syncthreads();
    float s = l2b[t];
    const float* wr = l2w + t * 128;
#pragma unroll 8
    for (int c = 0; c < 128; c++) s += gx[c] * wr[c];
    hid[t] = fmaxf(s, 0.f);
    __syncthreads();
    if (t < 5) {
        float s2 = l3b[t];
        const float* wr3 = l3w + t * 64;
#pragma unroll 8
        for (int j = 0; j < 64; j++) s2 += hid[j] * wr3[j];
        out[g * 5 + t] = s2;
    }
}

// ---------------- launcher ----------------
extern "C" void kernel_launch(void* const* d_in, const int* in_sizes, int n_in,
                              void* d_out, int out_size) {
    int wb = (n_in > 4 && in_sizes[4] == 216) ? 4 : 5;  // detect scalar num_graphs presence

    const float* x     = (const float*)d_in[0];
    const int*   ei    = (const int*)d_in[1];     // int32
    const float* ea    = (const float*)d_in[2];
    const int*   batch = (const int*)d_in[3];
    const float* c1w = (const float*)d_in[wb + 0];
    const float* c1b = (const float*)d_in[wb + 1];
    const float* c2w = (const float*)d_in[wb + 2];
    const float* c2b = (const float*)d_in[wb + 3];
    const float* l1w = (const float*)d_in[wb + 4];
    const float* l1b = (const float*)d_in[wb + 5];
    const float* gam = (const float*)d_in[wb + 6];
    const float* bet = (const float*)d_in[wb + 7];
    const float* l2w = (const float*)d_in[wb + 8];
    const float* l2b = (const float*)d_in[wb + 9];
    const float* l3w = (const float*)d_in[wb + 10];
    const float* l3b = (const float*)d_in[wb + 11];

    int n = in_sizes[0] / 1083;       // 50000
    int E = in_sizes[1] / 2;          // 1600000
    int G = (out_size - n * 128) / 5; // 512
    float* out = (float*)d_out;

    k_zero<<<(GMAXG * 128 + 255) / 256, 256>>>(n);
    k_cnn<<<(n + 1) / 2, 256>>>(x, c1w, c1b, c2w, c2b, n);
    k_deg<<<(E + 255) / 256, 256>>>(ei, ea, E);
    k_dinv<<<(n + 255) / 256, 256>>>(n);
    k_scan<<<1, 1024>>>(n);
    k_csr<<<(E + 255) / 256, 256>>>(ei, ea, E);
    k_l1<<<(n + 127) / 128, 256>>>(l1w, l1b, n);

    int hopBlocks = (n * 32 + 255) / 256;
    k_hop<<<hopBlocks, 256>>>(0, n);
    k_hop<<<hopBlocks, 256>>>(1, n);

    k_bnstats<<<(n + 127) / 128, 256>>>(n);
    k_bnfin<<<1, 128>>>(gam, bet, 1.0f / (float)n);
    k_pool<<<(n * 32 + 255) / 256, 256>>>(batch, out, n);
    k_gcnt<<<(n + 255) / 256, 256>>>(batch, n);
    k_mlp<<<G, 64>>>(l2w, l2b, l3w, l3b, out);
}

// round 4
// speedup vs baseline: 3.6407x; 2.5259x over previous
#include <cuda_runtime.h>
#include <cuda_bf16.h>

// ---------------- static scratch (no runtime allocation allowed) ----------------
#define NMAX 50048
#define EMAX 1664000
#define GMAXG 512

__device__ float g_feat[(size_t)NMAX * 245];   // CNN flattened features
__device__ float g_h0[(size_t)NMAX * 128];     // encoder output (APPNP h0)
__device__ float g_h1[(size_t)NMAX * 128];     // hop1 result
__device__ float g_h2[(size_t)NMAX * 128];     // hop2 result
__device__ float g_deg[NMAX];
__device__ float g_dinv[NMAX];
__device__ int   g_indeg[NMAX];
__device__ int   g_off[NMAX + 1];
__device__ int   g_cur[NMAX];
__device__ int2  g_edge[EMAX];                 // (src, weight-bits), CSR by dest
__device__ float g_bnsum[128];
__device__ float g_bnsq[128];
__device__ float g_ab[256];                    // [0:128)=scale a, [128:256)=shift b
__device__ float g_gsum[GMAXG * 128];
__device__ float g_gcnt[GMAXG];

// ---------------- zero init ----------------
__global__ void k_zero(int n) {
    int i = blockIdx.x * blockDim.x + threadIdx.x;
    if (i < n) { g_deg[i] = 0.f; g_indeg[i] = 0; }
    if (i < 128) { g_bnsum[i] = 0.f; g_bnsq[i] = 0.f; }
    if (i < GMAXG * 128) g_gsum[i] = 0.f;
    if (i < GMAXG) g_gcnt[i] = 0.f;
}

// ---------------- CNN encoder: sliding-window register rows, 7 nodes / block ----
// smem layout (floats): w1[224] | w2[1008] | xs[7*1083] | c1s[7*2312]
#define CNN_NPB 7
#define SM_W1   0
#define SM_W2   224
#define SM_XS   1232
#define SM_C1S  (1232 + CNN_NPB * 1083)
#define CNN_SMEM_FLOATS (SM_C1S + CNN_NPB * 2312)

__global__ __launch_bounds__(256) void k_cnn(
    const float* __restrict__ x,
    const float* __restrict__ c1w, const float* __restrict__ c1b,
    const float* __restrict__ c2w, const float* __restrict__ c2b, int n)
{
    extern __shared__ float sm[];
    float* w1  = sm + SM_W1;
    float* w2  = sm + SM_W2;
    float* xs  = sm + SM_XS;
    float* c1s = sm + SM_C1S;

    int t = threadIdx.x;
    int node0 = blockIdx.x * CNN_NPB;
    int nLocal = n - node0; if (nLocal > CNN_NPB) nLocal = CNN_NPB;
    if (nLocal <= 0) return;

    for (int i = t; i < 216; i += 256) w1[i] = c1w[i];
    if (t < 8) w1[216 + t] = c1b[t];
    for (int i = t; i < 1000; i += 256) w2[i] = c2w[i];
    if (t < 5) w2[1000 + t] = c2b[t];

    // nodes are contiguous: coalesced bulk copy
    int totx = nLocal * 1083;
    const float* xp = x + (size_t)node0 * 1083;
    for (int i = t; i < totx; i += 256) xs[i] = xp[i];
    __syncthreads();

    // ---- conv1: task = (node, oc, oy); thread computes 17-wide row ----
    int tasks1 = nLocal * 136;
    for (int tt = t; tt < tasks1; tt += 256) {
        int nd  = tt / 136;
        int rid = tt - nd * 136;
        int oc  = rid / 17;
        int oy  = rid - oc * 17;
        const float* xb = xs + nd * 1083;
        float acc[17];
        float bias = w1[216 + oc];
#pragma unroll
        for (int ox = 0; ox < 17; ox++) acc[ox] = bias;
#pragma unroll
        for (int ic = 0; ic < 3; ic++) {
#pragma unroll
            for (int ky = 0; ky < 3; ky++) {
                const float* rowp = xb + ic * 361 + (oy + ky) * 19;
                float rr[19];
#pragma unroll
                for (int j = 0; j < 19; j++) rr[j] = rowp[j];
                const float* wp = w1 + oc * 27 + ic * 9 + ky * 3;
                float wa = wp[0], wbv = wp[1], wc = wp[2];
#pragma unroll
                for (int ox = 0; ox < 17; ox++)
                    acc[ox] += rr[ox] * wa + rr[ox + 1] * wbv + rr[ox + 2] * wc;
            }
        }
        float* op = c1s + nd * 2312 + oc * 289 + oy * 17;
#pragma unroll
        for (int ox = 0; ox < 17; ox++) op[ox] = fmaxf(acc[ox], 0.f);
    }
    __syncthreads();

    // ---- conv2: task = (node, oc, oy); thread computes 7-wide row (stride 2) ----
    int tasks2 = nLocal * 35;
    for (int tt = t; tt < tasks2; tt += 256) {
        int nd  = tt / 35;
        int rid = tt - nd * 35;
        int oc  = rid / 7;
        int oy  = rid - oc * 7;
        const float* ib = c1s + nd * 2312;
        float acc[7];
        float bias = w2[1000 + oc];
#pragma unroll
        for (int ox = 0; ox < 7; ox++) acc[ox] = bias;
        for (int ic = 0; ic < 8; ic++) {
#pragma unroll
            for (int ky = 0; ky < 5; ky++) {
                const float* rowp = ib + ic * 289 + (oy * 2 + ky) * 17;
                float rr[17];
#pragma unroll
                for (int j = 0; j < 17; j++) rr[j] = rowp[j];
                const float* wp = w2 + oc * 200 + ic * 25 + ky * 5;
                float wv[5];
#pragma unroll
                for (int kx = 0; kx < 5; kx++) wv[kx] = wp[kx];
#pragma unroll
                for (int ox = 0; ox < 7; ox++) {
#pragma unroll
                    for (int kx = 0; kx < 5; kx++)
                        acc[ox] += rr[ox * 2 + kx] * wv[kx];
                }
            }
        }
        float* fp = g_feat + (size_t)(node0 + nd) * 245 + oc * 49 + oy * 7;
#pragma unroll
        for (int ox = 0; ox < 7; ox++) fp[ox] = fmaxf(acc[ox], 0.f);
    }
}

// ---------------- degree (weighted float + integer in-degree) ----------------
__global__ void k_deg(const int* __restrict__ ei, const float* __restrict__ ea, int E) {
    int e = blockIdx.x * blockDim.x + threadIdx.x;
    if (e >= E) return;
    int c = ei[E + e];
    atomicAdd(&g_deg[c], ea[e]);
    atomicAdd(&g_indeg[c], 1);
}

__global__ void k_dinv(int n) {
    int i = blockIdx.x * blockDim.x + threadIdx.x;
    if (i >= n) return;
    float d = g_deg[i];
    g_dinv[i] = (d > 0.f) ? rsqrtf(d) : 0.f;
}

// ---------------- single-block exclusive prefix scan of in-degrees ----------------
__global__ __launch_bounds__(1024) void k_scan(int n) {
    __shared__ int buf[2][1024];
    __shared__ int s_carry;
    int t = threadIdx.x;
    if (t == 0) s_carry = 0;
    __syncthreads();
    for (int base = 0; base < n; base += 1024) {
        int v = (base + t < n) ? g_indeg[base + t] : 0;
        buf[0][t] = v;
        __syncthreads();
        int src = 0;
#pragma unroll
        for (int d = 1; d < 1024; d <<= 1) {
            int val = buf[src][t];
            if (t >= d) val += buf[src][t - d];
            buf[1 - src][t] = val;
            src = 1 - src;
            __syncthreads();
        }
        int inc = buf[src][t];
        int carry = s_carry;
        if (base + t < n) {
            int excl = carry + inc - v;
            g_off[base + t] = excl;
            g_cur[base + t] = excl;
        }
        __syncthreads();
        if (t == 1023) s_carry = carry + inc;
        __syncthreads();
    }
    if (t == 0) g_off[n] = s_carry;
}

// ---------------- CSR build: norm + edge record placement ----------------
__global__ void k_csr(const int* __restrict__ ei, const float* __restrict__ ea, int E) {
    int e = blockIdx.x * blockDim.x + threadIdx.x;
    if (e >= E) return;
    int r = ei[e];
    int c = ei[E + e];
    float nrm = 0.2f * g_dinv[r] * ea[e] * g_dinv[c];  // fold (1-alpha)=0.2
    int pos = atomicAdd(&g_cur[c], 1);
    g_edge[pos] = make_int2(r, __float_as_int(nrm));
}

// ---------------- l1: feat[n,245] @ l1w.T[245,128] + b, relu -> h0 ----------------
__global__ __launch_bounds__(256) void k_l1(const float* __restrict__ l1w,
                                            const float* __restrict__ l1b, int n)
{
    __shared__ float As[16][128];
    __shared__ float Bs[16][128];
    int t = threadIdx.x;
    int tx = t & 15, ty = t >> 4;
    float acc[8][8];
#pragma unroll
    for (int i = 0; i < 8; i++)
#pragma unroll
        for (int j = 0; j < 8; j++) acc[i][j] = 0.f;

    int rowBase = blockIdx.x * 128;
    for (int k0 = 0; k0 < 245; k0 += 16) {
#pragma unroll
        for (int i = 0; i < 8; i++) {
            int e = t + i * 256;
            int m = e >> 4, kk = e & 15;
            int node = rowBase + m, k = k0 + kk;
            As[kk][m] = (node < n && k < 245) ? g_feat[(size_t)node * 245 + k] : 0.f;
            Bs[kk][m] = (k < 245) ? l1w[m * 245 + k] : 0.f;
        }
        __syncthreads();
#pragma unroll
        for (int kk = 0; kk < 16; kk++) {
            float a[8], b[8];
#pragma unroll
            for (int i = 0; i < 8; i++) a[i] = As[kk][ty + i * 16];
#pragma unroll
            for (int j = 0; j < 8; j++) b[j] = Bs[kk][tx + j * 16];
#pragma unroll
            for (int i = 0; i < 8; i++)
#pragma unroll
                for (int j = 0; j < 8; j++) acc[i][j] += a[i] * b[j];
        }
        __syncthreads();
    }
#pragma unroll
    for (int i = 0; i < 8; i++) {
        int node = rowBase + ty + i * 16;
        if (node >= n) continue;
#pragma unroll
        for (int j = 0; j < 8; j++) {
            int col = tx + j * 16;
            g_h0[(size_t)node * 128 + col] = fmaxf(acc[i][j] + l1b[col], 0.f);
        }
    }
}

// ---------------- APPNP hop (gather, no atomics): one warp per dest node ----------
__global__ __launch_bounds__(256) void k_hop(int which, int n) {
    int wid = (blockIdx.x * 256 + threadIdx.x) >> 5;
    int lane = threadIdx.x & 31;
    if (wid >= n) return;
    const float4* hin = (const float4*)(which ? g_h1 : g_h0);
    float4* hout = (float4*)(which ? g_h2 : g_h1);
    int off0 = g_off[wid], off1 = g_off[wid + 1];

    float4 acc = make_float4(0.f, 0.f, 0.f, 0.f);
    int e = off0;
    for (; e + 2 <= off1; e += 2) {
        int2 ra = g_edge[e];
        int2 rb = g_edge[e + 1];
        float4 v0 = hin[(size_t)ra.x * 32 + lane];
        float4 v1 = hin[(size_t)rb.x * 32 + lane];
        float w0 = __int_as_float(ra.y);
        float w1 = __int_as_float(rb.y);
        acc.x += w0 * v0.x; acc.y += w0 * v0.y; acc.z += w0 * v0.z; acc.w += w0 * v0.w;
        acc.x += w1 * v1.x; acc.y += w1 * v1.y; acc.z += w1 * v1.z; acc.w += w1 * v1.w;
    }
    if (e < off1) {
        int2 ra = g_edge[e];
        float4 v0 = hin[(size_t)ra.x * 32 + lane];
        float w0 = __int_as_float(ra.y);
        acc.x += w0 * v0.x; acc.y += w0 * v0.y; acc.z += w0 * v0.z; acc.w += w0 * v0.w;
    }
    float4 h0v = ((const float4*)g_h0)[(size_t)wid * 32 + lane];
    float4 o;
    o.x = acc.x + 0.8f * h0v.x;
    o.y = acc.y + 0.8f * h0v.y;
    o.z = acc.z + 0.8f * h0v.z;
    o.w = acc.w + 0.8f * h0v.w;
    hout[(size_t)wid * 32 + lane] = o;
}

// ---------------- BN stats over h2 (channel-stationary) ----------------
__global__ __launch_bounds__(256) void k_bnstats(int n) {
    int c = threadIdx.x & 127;
    int sub = threadIdx.x >> 7;
    int n0 = blockIdx.x * 128;
    float s = 0.f, sq = 0.f;
    for (int k = sub; k < 128; k += 2) {
        int node = n0 + k;
        if (node < n) {
            float v = g_h2[(size_t)node * 128 + c];
            s += v; sq += v * v;
        }
    }
    __shared__ float ss[256], sqq[256];
    ss[threadIdx.x] = s; sqq[threadIdx.x] = sq;
    __syncthreads();
    if (threadIdx.x < 128) {
        atomicAdd(&g_bnsum[c], ss[threadIdx.x] + ss[threadIdx.x + 128]);
        atomicAdd(&g_bnsq[c], sqq[threadIdx.x] + sqq[threadIdx.x + 128]);
    }
}

__global__ void k_bnfin(const float* __restrict__ gamma, const float* __restrict__ beta,
                        float invN) {
    int c = threadIdx.x;
    float mean = g_bnsum[c] * invN;
    float var = g_bnsq[c] * invN - mean * mean;
    float inv = rsqrtf(var + 1e-5f);
    float a = gamma[c] * inv;
    g_ab[c] = a;
    g_ab[128 + c] = beta[c] - mean * a;
}

// ---------------- normalize + write node_x + pool scatter ----------------
__global__ void k_pool(const int* __restrict__ batch, float* __restrict__ out, int n) {
    int idx = blockIdx.x * blockDim.x + threadIdx.x;
    if (idx >= n * 32) return;
    int node = idx >> 5, q = idx & 31;
    int c = q * 4;
    float4 v = ((const float4*)g_h2)[idx];
    float4 r;
    r.x = v.x * g_ab[c + 0] + g_ab[128 + c + 0];
    r.y = v.y * g_ab[c + 1] + g_ab[128 + c + 1];
    r.z = v.z * g_ab[c + 2] + g_ab[128 + c + 2];
    r.w = v.w * g_ab[c + 3] + g_ab[128 + c + 3];
    ((float4*)out)[640 + idx] = r;   // node_x starts at float offset 2560
    int g = batch[node];
    float* gp = g_gsum + (size_t)g * 128 + c;
    atomicAdd(gp + 0, r.x);
    atomicAdd(gp + 1, r.y);
    atomicAdd(gp + 2, r.z);
    atomicAdd(gp + 3, r.w);
}

__global__ void k_gcnt(const int* __restrict__ batch, int n) {
    int i = blockIdx.x * blockDim.x + threadIdx.x;
    if (i >= n) return;
    atomicAdd(&g_gcnt[batch[i]], 1.0f);
}

// ---------------- graph MLP classifier ----------------
__global__ __launch_bounds__(64) void k_mlp(const float* __restrict__ l2w,
                                            const float* __restrict__ l2b,
                                            const float* __restrict__ l3w,
                                            const float* __restrict__ l3b,
                                            float* __restrict__ out) {
    int g = blockIdx.x, t = threadIdx.x;
    __shared__ float gx[128], hid[64];
    float cnt = fmaxf(g_gcnt[g], 1.f);
    float ic = 1.f / cnt;
    gx[t]      = g_gsum[(size_t)g * 128 + t] * ic;
    gx[t + 64] = g_gsum[(size_t)g * 128 + 64 + t] * ic;
    __syncthreads();
    float s = l2b[t];
    const float* wr = l2w + t * 128;
#pragma unroll 8
    for (int c = 0; c < 128; c++) s += gx[c] * wr[c];
    hid[t] = fmaxf(s, 0.f);
    __syncthreads();
    if (t < 5) {
        float s2 = l3b[t];
        const float* wr3 = l3w + t * 64;
#pragma unroll 8
        for (int j = 0; j < 64; j++) s2 += hid[j] * wr3[j];
        out[g * 5 + t] = s2;
    }
}

// ---------------- launcher ----------------
extern "C" void kernel_launch(void* const* d_in, const int* in_sizes, int n_in,
                              void* d_out, int out_size) {
    int wb = (n_in > 4 && in_sizes[4] == 216) ? 4 : 5;

    const float* x     = (const float*)d_in[0];
    const int*   ei    = (const int*)d_in[1];
    const float* ea    = (const float*)d_in[2];
    const int*   batch = (const int*)d_in[3];
    const float* c1w = (const float*)d_in[wb + 0];
    const float* c1b = (const float*)d_in[wb + 1];
    const float* c2w = (const float*)d_in[wb + 2];
    const float* c2b = (const float*)d_in[wb + 3];
    const float* l1w = (const float*)d_in[wb + 4];
    const float* l1b = (const float*)d_in[wb + 5];
    const float* gam = (const float*)d_in[wb + 6];
    const float* bet = (const float*)d_in[wb + 7];
    const float* l2w = (const float*)d_in[wb + 8];
    const float* l2b = (const float*)d_in[wb + 9];
    const float* l3w = (const float*)d_in[wb + 10];
    const float* l3b = (const float*)d_in[wb + 11];

    int n = in_sizes[0] / 1083;       // 50000
    int E = in_sizes[1] / 2;          // 1600000
    int G = (out_size - n * 128) / 5; // 512
    float* out = (float*)d_out;

    int cnnSmem = CNN_SMEM_FLOATS * 4;
    cudaFuncSetAttribute(k_cnn, cudaFuncAttributeMaxDynamicSharedMemorySize, cnnSmem);

    // order chosen so the hot kernel sits at the ncu sampling index
    k_zero<<<(GMAXG * 128 + 255) / 256, 256>>>(n);
    k_deg<<<(E + 255) / 256, 256>>>(ei, ea, E);
    k_dinv<<<(n + 255) / 256, 256>>>(n);
    k_cnn<<<(n + CNN_NPB - 1) / CNN_NPB, 256, cnnSmem>>>(x, c1w, c1b, c2w, c2b, n);
    k_scan<<<1, 1024>>>(n);
    k_csr<<<(E + 255) / 256, 256>>>(ei, ea, E);
    k_l1<<<(n + 127) / 128, 256>>>(l1w, l1b, n);

    int hopBlocks = (n * 32 + 255) / 256;
    k_hop<<<hopBlocks, 256>>>(0, n);
    k_hop<<<hopBlocks, 256>>>(1, n);

    k_bnstats<<<(n + 127) / 128, 256>>>(n);
    k_bnfin<<<1, 128>>>(gam, bet, 1.0f / (float)n);
    k_pool<<<(n * 32 + 255) / 256, 256>>>(batch, out, n);
    k_gcnt<<<(n + 255) / 256, 256>>>(batch, n);
    k_mlp<<<G, 64>>>(l2w, l2b, l3w, l3b, out);
}

// round 5
// speedup vs baseline: 4.0519x; 1.1129x over previous
#include <cuda_runtime.h>
#include <cuda_bf16.h>

// ---------------- static scratch (no runtime allocation allowed) ----------------
#define NMAX 50048
#define EMAX 1664000
#define GMAXG 512

__device__ float g_feat[(size_t)NMAX * 245];
__device__ float g_h0[(size_t)NMAX * 128];
__device__ float g_h1[(size_t)NMAX * 128];
__device__ float g_h2[(size_t)NMAX * 128];
__device__ float g_deg[NMAX];
__device__ float g_dinv[NMAX];
__device__ int   g_indeg[NMAX];
__device__ int   g_off[NMAX + 1];
__device__ int   g_cur[NMAX];
__device__ int2  g_edge[EMAX];
__device__ float g_bnsum[128];
__device__ float g_bnsq[128];
__device__ float g_ab[256];
__device__ float g_gsum[GMAXG * 128];
__device__ float g_gcnt[GMAXG];

// ---------------- zero init ----------------
__global__ void k_zero(int n) {
    int i = blockIdx.x * blockDim.x + threadIdx.x;
    if (i < n) { g_deg[i] = 0.f; g_indeg[i] = 0; }
    if (i < 128) { g_bnsum[i] = 0.f; g_bnsq[i] = 0.f; }
    if (i < GMAXG * 128) g_gsum[i] = 0.f;
    if (i < GMAXG) g_gcnt[i] = 0.f;
}

// ---------------- CNN encoder: oc-grouped register tiles, 7 nodes / block ------
// smem layout (floats): w1[224] | w2[1008] | xs[7*1083] | c1s[7*2312]
#define CNN_NPB 7
#define SM_W1   0
#define SM_W2   224
#define SM_XS   1232
#define SM_C1S  (1232 + CNN_NPB * 1083)
#define CNN_SMEM_FLOATS (SM_C1S + CNN_NPB * 2312)

__global__ __launch_bounds__(256, 2) void k_cnn(
    const float* __restrict__ x,
    const float* __restrict__ c1w, const float* __restrict__ c1b,
    const float* __restrict__ c2w, const float* __restrict__ c2b, int n)
{
    extern __shared__ float sm[];
    float* w1  = sm + SM_W1;
    float* w2  = sm + SM_W2;
    float* xs  = sm + SM_XS;
    float* c1s = sm + SM_C1S;

    int t = threadIdx.x;
    int node0 = blockIdx.x * CNN_NPB;
    int nLocal = n - node0; if (nLocal > CNN_NPB) nLocal = CNN_NPB;
    if (nLocal <= 0) return;

    for (int i = t; i < 216; i += 256) w1[i] = c1w[i];
    if (t < 8) w1[216 + t] = c1b[t];
    for (int i = t; i < 1000; i += 256) w2[i] = c2w[i];
    if (t < 5) w2[1000 + t] = c2b[t];

    int totx = nLocal * 1083;
    const float* xp = x + (size_t)node0 * 1083;
    for (int i = t; i < totx; i += 256) xs[i] = xp[i];
    __syncthreads();

    // ---- conv1: task = (node, oy, ocg of 4); thread computes 4x17 outputs ----
    int tasks1 = nLocal * 34;     // 17 oy * 2 oc-groups
    for (int tt = t; tt < tasks1; tt += 256) {
        int nd  = tt / 34;
        int rid = tt - nd * 34;
        int ocg = rid / 17;       // 0/1 -> ocs [0..3] / [4..7]
        int oy  = rid - ocg * 17;
        int ocb = ocg * 4;
        const float* xb = xs + nd * 1083;

        float acc[4][17];
#pragma unroll
        for (int o = 0; o < 4; o++) {
            float bias = w1[216 + ocb + o];
#pragma unroll
            for (int ox = 0; ox < 17; ox++) acc[o][ox] = bias;
        }
#pragma unroll
        for (int ic = 0; ic < 3; ic++) {
#pragma unroll
            for (int ky = 0; ky < 3; ky++) {
                const float* rowp = xb + ic * 361 + (oy + ky) * 19;
                float rr[19];
#pragma unroll
                for (int j = 0; j < 19; j++) rr[j] = rowp[j];
#pragma unroll
                for (int o = 0; o < 4; o++) {
                    const float* wp = w1 + (ocb + o) * 27 + ic * 9 + ky * 3;
                    float wa = wp[0], wbv = wp[1], wc = wp[2];
#pragma unroll
                    for (int ox = 0; ox < 17; ox++)
                        acc[o][ox] += rr[ox] * wa + rr[ox + 1] * wbv + rr[ox + 2] * wc;
                }
            }
        }
#pragma unroll
        for (int o = 0; o < 4; o++) {
            float* op = c1s + nd * 2312 + (ocb + o) * 289 + oy * 17;
#pragma unroll
            for (int ox = 0; ox < 17; ox++) op[ox] = fmaxf(acc[o][ox], 0.f);
        }
    }
    __syncthreads();

    // ---- conv2: 4 lanes per (node, oy); each lane handles 2 input channels,
    //      computes full acc[5 oc][7 ox], then xor-shuffle reduce over ic-split.
    {
        int icg = t & 3;
        int pid = t >> 2;               // 0..63
        int nd  = pid / 7;
        int oy  = pid - nd * 7;
        bool valid = (nd < nLocal);
        int ndc = valid ? nd : 0;
        const float* ib = c1s + ndc * 2312;

        float acc[35];
#pragma unroll
        for (int j = 0; j < 35; j++) acc[j] = 0.f;

#pragma unroll
        for (int ii = 0; ii < 2; ii++) {
            int ic = icg * 2 + ii;
#pragma unroll
            for (int ky = 0; ky < 5; ky++) {
                const float* rowp = ib + ic * 289 + (oy * 2 + ky) * 17;
                float rr[17];
#pragma unroll
                for (int j = 0; j < 17; j++) rr[j] = rowp[j];
#pragma unroll
                for (int oc = 0; oc < 5; oc++) {
                    const float* wp = w2 + oc * 200 + ic * 25 + ky * 5;
                    float wv[5];
#pragma unroll
                    for (int kx = 0; kx < 5; kx++) wv[kx] = wp[kx];
#pragma unroll
                    for (int ox = 0; ox < 7; ox++) {
#pragma unroll
                        for (int kx = 0; kx < 5; kx++)
                            acc[oc * 7 + ox] += rr[ox * 2 + kx] * wv[kx];
                    }
                }
            }
        }
        // reduce across 4 ic-groups (lanes t^1, t^2 share (node,oy))
#pragma unroll
        for (int j = 0; j < 35; j++) {
            acc[j] += __shfl_xor_sync(0xffffffff, acc[j], 1);
            acc[j] += __shfl_xor_sync(0xffffffff, acc[j], 2);
        }
        if (valid && icg == 0) {
            float* fp = g_feat + (size_t)(node0 + nd) * 245 + oy * 7;
#pragma unroll
            for (int oc = 0; oc < 5; oc++) {
                float bias = w2[1000 + oc];
#pragma unroll
                for (int ox = 0; ox < 7; ox++)
                    fp[oc * 49 + ox] = fmaxf(acc[oc * 7 + ox] + bias, 0.f);
            }
        }
    }
}

// ---------------- degree (weighted float + integer in-degree) ----------------
__global__ void k_deg(const int* __restrict__ ei, const float* __restrict__ ea, int E) {
    int e = blockIdx.x * blockDim.x + threadIdx.x;
    if (e >= E) return;
    int c = ei[E + e];
    atomicAdd(&g_deg[c], ea[e]);
    atomicAdd(&g_indeg[c], 1);
}

__global__ void k_dinv(int n) {
    int i = blockIdx.x * blockDim.x + threadIdx.x;
    if (i >= n) return;
    float d = g_deg[i];
    g_dinv[i] = (d > 0.f) ? rsqrtf(d) : 0.f;
}

// ---------------- single-block exclusive prefix scan of in-degrees ----------------
__global__ __launch_bounds__(1024) void k_scan(int n) {
    __shared__ int buf[2][1024];
    __shared__ int s_carry;
    int t = threadIdx.x;
    if (t == 0) s_carry = 0;
    __syncthreads();
    for (int base = 0; base < n; base += 1024) {
        int v = (base + t < n) ? g_indeg[base + t] : 0;
        buf[0][t] = v;
        __syncthreads();
        int src = 0;
#pragma unroll
        for (int d = 1; d < 1024; d <<= 1) {
            int val = buf[src][t];
            if (t >= d) val += buf[src][t - d];
            buf[1 - src][t] = val;
            src = 1 - src;
            __syncthreads();
        }
        int inc = buf[src][t];
        int carry = s_carry;
        if (base + t < n) {
            int excl = carry + inc - v;
            g_off[base + t] = excl;
            g_cur[base + t] = excl;
        }
        __syncthreads();
        if (t == 1023) s_carry = carry + inc;
        __syncthreads();
    }
    if (t == 0) g_off[n] = s_carry;
}

// ---------------- CSR build ----------------
__global__ void k_csr(const int* __restrict__ ei, const float* __restrict__ ea, int E) {
    int e = blockIdx.x * blockDim.x + threadIdx.x;
    if (e >= E) return;
    int r = ei[e];
    int c = ei[E + e];
    float nrm = 0.2f * g_dinv[r] * ea[e] * g_dinv[c];
    int pos = atomicAdd(&g_cur[c], 1);
    g_edge[pos] = make_int2(r, __float_as_int(nrm));
}

// ---------------- l1: feat[n,245] @ l1w.T + b, relu -> h0 ----------------
__global__ __launch_bounds__(256) void k_l1(const float* __restrict__ l1w,
                                            const float* __restrict__ l1b, int n)
{
    __shared__ float As[16][128];
    __shared__ float Bs[16][128];
    int t = threadIdx.x;
    int tx = t & 15, ty = t >> 4;
    float acc[8][8];
#pragma unroll
    for (int i = 0; i < 8; i++)
#pragma unroll
        for (int j = 0; j < 8; j++) acc[i][j] = 0.f;

    int rowBase = blockIdx.x * 128;
    for (int k0 = 0; k0 < 245; k0 += 16) {
#pragma unroll
        for (int i = 0; i < 8; i++) {
            int e = t + i * 256;
            int m = e >> 4, kk = e & 15;
            int node = rowBase + m, k = k0 + kk;
            As[kk][m] = (node < n && k < 245) ? g_feat[(size_t)node * 245 + k] : 0.f;
            Bs[kk][m] = (k < 245) ? l1w[m * 245 + k] : 0.f;
        }
        __syncthreads();
#pragma unroll
        for (int kk = 0; kk < 16; kk++) {
            float a[8], b[8];
#pragma unroll
            for (int i = 0; i < 8; i++) a[i] = As[kk][ty + i * 16];
#pragma unroll
            for (int j = 0; j < 8; j++) b[j] = Bs[kk][tx + j * 16];
#pragma unroll
            for (int i = 0; i < 8; i++)
#pragma unroll
                for (int j = 0; j < 8; j++) acc[i][j] += a[i] * b[j];
        }
        __syncthreads();
    }
#pragma unroll
    for (int i = 0; i < 8; i++) {
        int node = rowBase + ty + i * 16;
        if (node >= n) continue;
#pragma unroll
        for (int j = 0; j < 8; j++) {
            int col = tx + j * 16;
            g_h0[(size_t)node * 128 + col] = fmaxf(acc[i][j] + l1b[col], 0.f);
        }
    }
}

// ---------------- APPNP hop (gather, no atomics): one warp per dest node -------
__global__ __launch_bounds__(256) void k_hop(int which, int n) {
    int wid = (blockIdx.x * 256 + threadIdx.x) >> 5;
    int lane = threadIdx.x & 31;
    if (wid >= n) return;
    const float4* hin = (const float4*)(which ? g_h1 : g_h0);
    float4* hout = (float4*)(which ? g_h2 : g_h1);
    int off0 = g_off[wid], off1 = g_off[wid + 1];

    float4 acc = make_float4(0.f, 0.f, 0.f, 0.f);
    int e = off0;
    for (; e + 2 <= off1; e += 2) {
        int2 ra = g_edge[e];
        int2 rb = g_edge[e + 1];
        float4 v0 = hin[(size_t)ra.x * 32 + lane];
        float4 v1 = hin[(size_t)rb.x * 32 + lane];
        float w0 = __int_as_float(ra.y);
        float w1 = __int_as_float(rb.y);
        acc.x += w0 * v0.x; acc.y += w0 * v0.y; acc.z += w0 * v0.z; acc.w += w0 * v0.w;
        acc.x += w1 * v1.x; acc.y += w1 * v1.y; acc.z += w1 * v1.z; acc.w += w1 * v1.w;
    }
    if (e < off1) {
        int2 ra = g_edge[e];
        float4 v0 = hin[(size_t)ra.x * 32 + lane];
        float w0 = __int_as_float(ra.y);
        acc.x += w0 * v0.x; acc.y += w0 * v0.y; acc.z += w0 * v0.z; acc.w += w0 * v0.w;
    }
    float4 h0v = ((const float4*)g_h0)[(size_t)wid * 32 + lane];
    float4 o;
    o.x = acc.x + 0.8f * h0v.x;
    o.y = acc.y + 0.8f * h0v.y;
    o.z = acc.z + 0.8f * h0v.z;
    o.w = acc.w + 0.8f * h0v.w;
    hout[(size_t)wid * 32 + lane] = o;
}

// ---------------- BN stats over h2 ----------------
__global__ __launch_bounds__(256) void k_bnstats(int n) {
    int c = threadIdx.x & 127;
    int sub = threadIdx.x >> 7;
    int n0 = blockIdx.x * 128;
    float s = 0.f, sq = 0.f;
    for (int k = sub; k < 128; k += 2) {
        int node = n0 + k;
        if (node < n) {
            float v = g_h2[(size_t)node * 128 + c];
            s += v; sq += v * v;
        }
    }
    __shared__ float ss[256], sqq[256];
    ss[threadIdx.x] = s; sqq[threadIdx.x] = sq;
    __syncthreads();
    if (threadIdx.x < 128) {
        atomicAdd(&g_bnsum[c], ss[threadIdx.x] + ss[threadIdx.x + 128]);
        atomicAdd(&g_bnsq[c], sqq[threadIdx.x] + sqq[threadIdx.x + 128]);
    }
}

__global__ void k_bnfin(const float* __restrict__ gamma, const float* __restrict__ beta,
                        float invN) {
    int c = threadIdx.x;
    float mean = g_bnsum[c] * invN;
    float var = g_bnsq[c] * invN - mean * mean;
    float inv = rsqrtf(var + 1e-5f);
    float a = gamma[c] * inv;
    g_ab[c] = a;
    g_ab[128 + c] = beta[c] - mean * a;
}

// ---------------- normalize + write node_x + pool scatter ----------------
__global__ void k_pool(const int* __restrict__ batch, float* __restrict__ out, int n) {
    int idx = blockIdx.x * blockDim.x + threadIdx.x;
    if (idx >= n * 32) return;
    int node = idx >> 5, q = idx & 31;
    int c = q * 4;
    float4 v = ((const float4*)g_h2)[idx];
    float4 r;
    r.x = v.x * g_ab[c + 0] + g_ab[128 + c + 0];
    r.y = v.y * g_ab[c + 1] + g_ab[128 + c + 1];
    r.z = v.z * g_ab[c + 2] + g_ab[128 + c + 2];
    r.w = v.w * g_ab[c + 3] + g_ab[128 + c + 3];
    ((float4*)out)[640 + idx] = r;
    int g = batch[node];
    float* gp = g_gsum + (size_t)g * 128 + c;
    atomicAdd(gp + 0, r.x);
    atomicAdd(gp + 1, r.y);
    atomicAdd(gp + 2, r.z);
    atomicAdd(gp + 3, r.w);
}

__global__ void k_gcnt(const int* __restrict__ batch, int n) {
    int i = blockIdx.x * blockDim.x + threadIdx.x;
    if (i >= n) return;
    atomicAdd(&g_gcnt[batch[i]], 1.0f);
}

// ---------------- graph MLP classifier ----------------
__global__ __launch_bounds__(64) void k_mlp(const float* __restrict__ l2w,
                                            const float* __restrict__ l2b,
                                            const float* __restrict__ l3w,
                                            const float* __restrict__ l3b,
                                            float* __restrict__ out) {
    int g = blockIdx.x, t = threadIdx.x;
    __shared__ float gx[128], hid[64];
    float cnt = fmaxf(g_gcnt[g], 1.f);
    float ic = 1.f / cnt;
    gx[t]      = g_gsum[(size_t)g * 128 + t] * ic;
    gx[t + 64] = g_gsum[(size_t)g * 128 + 64 + t] * ic;
    __syncthreads();
    float s = l2b[t];
    const float* wr = l2w + t * 128;
#pragma unroll 8
    for (int c = 0; c < 128; c++) s += gx[c] * wr[c];
    hid[t] = fmaxf(s, 0.f);
    __syncthreads();
    if (t < 5) {
        float s2 = l3b[t];
        const float* wr3 = l3w + t * 64;
#pragma unroll 8
        for (int j = 0; j < 64; j++) s2 += hid[j] * wr3[j];
        out[g * 5 + t] = s2;
    }
}

// ---------------- launcher ----------------
extern "C" void kernel_launch(void* const* d_in, const int* in_sizes, int n_in,
                              void* d_out, int out_size) {
    int wb = (n_in > 4 && in_sizes[4] == 216) ? 4 : 5;

    const float* x     = (const float*)d_in[0];
    const int*   ei    = (const int*)d_in[1];
    const float* ea    = (const float*)d_in[2];
    const int*   batch = (const int*)d_in[3];
    const float* c1w = (const float*)d_in[wb + 0];
    const float* c1b = (const float*)d_in[wb + 1];
    const float* c2w = (const float*)d_in[wb + 2];
    const float* c2b = (const float*)d_in[wb + 3];
    const float* l1w = (const float*)d_in[wb + 4];
    const float* l1b = (const float*)d_in[wb + 5];
    const float* gam = (const float*)d_in[wb + 6];
    const float* bet = (const float*)d_in[wb + 7];
    const float* l2w = (const float*)d_in[wb + 8];
    const float* l2b = (const float*)d_in[wb + 9];
    const float* l3w = (const float*)d_in[wb + 10];
    const float* l3b = (const float*)d_in[wb + 11];

    int n = in_sizes[0] / 1083;
    int E = in_sizes[1] / 2;
    int G = (out_size - n * 128) / 5;
    float* out = (float*)d_out;

    int cnnSmem = CNN_SMEM_FLOATS * 4;
    cudaFuncSetAttribute(k_cnn, cudaFuncAttributeMaxDynamicSharedMemorySize, cnnSmem);

    k_zero<<<(GMAXG * 128 + 255) / 256, 256>>>(n);
    k_deg<<<(E + 255) / 256, 256>>>(ei, ea, E);
    k_dinv<<<(n + 255) / 256, 256>>>(n);
    k_cnn<<<(n + CNN_NPB - 1) / CNN_NPB, 256, cnnSmem>>>(x, c1w, c1b, c2w, c2b, n);
    k_scan<<<1, 1024>>>(n);
    k_csr<<<(E + 255) / 256, 256>>>(ei, ea, E);
    k_l1<<<(n + 127) / 128, 256>>>(l1w, l1b, n);

    int hopBlocks = (n * 32 + 255) / 256;
    k_hop<<<hopBlocks, 256>>>(0, n);
    k_hop<<<hopBlocks, 256>>>(1, n);

    k_bnstats<<<(n + 127) / 128, 256>>>(n);
    k_bnfin<<<1, 128>>>(gam, bet, 1.0f / (float)n);
    k_pool<<<(n * 32 + 255) / 256, 256>>>(batch, out, n);
    k_gcnt<<<(n + 255) / 256, 256>>>(batch, n);
    k_mlp<<<G, 64>>>(l2w, l2b, l3w, l3b, out);
}